// round 1
// baseline (speedup 1.0000x reference)
#include <cuda_runtime.h>
#include <math.h>
#include <stdint.h>

// ---------------- problem constants ----------------
#define S_   2048
#define H_   1024
#define NH   16
#define HD   64
#define E_   8
#define F_   2048
#define T3H  3072

// ---------------- device scratch (allocation-free rule: __device__ globals) ----
__device__ float g_hn     [S_ * H_];
__device__ float g_qkv    [S_ * T3H];
__device__ float g_scores [(size_t)NH * S_ * S_];   // 256 MB, reused for probs
__device__ float g_attn   [S_ * H_];
__device__ float g_x1     [S_ * H_];
__device__ float g_hn2    [S_ * H_];
__device__ int   g_topi   [S_ * 2];
__device__ float g_topw   [S_ * 2];
__device__ int   g_cnt    [E_];
__device__ int   g_ltok   [E_ * S_];
__device__ int   g_lslot  [E_ * S_];
__device__ float g_lgate  [E_ * S_];
__device__ float g_h1     [(size_t)E_ * S_ * F_];   // 128 MB
__device__ float g_contrib[(size_t)S_ * 2 * H_];

// ---------------- LayerNorm ----------------
__global__ __launch_bounds__(256) void ln_kernel(
    const float* __restrict__ x, const float* __restrict__ w,
    const float* __restrict__ b, float* __restrict__ out)
{
    int row = blockIdx.x;
    int tid = threadIdx.x;
    const float4* xr = (const float4*)(x + (size_t)row * H_);
    float4 v = xr[tid];
    float s  = v.x + v.y + v.z + v.w;
    float ss = v.x*v.x + v.y*v.y + v.z*v.z + v.w*v.w;
    __shared__ float rs[256], rq[256];
    rs[tid] = s; rq[tid] = ss;
    __syncthreads();
    for (int o = 128; o > 0; o >>= 1) {
        if (tid < o) { rs[tid] += rs[tid + o]; rq[tid] += rq[tid + o]; }
        __syncthreads();
    }
    float mu   = rs[0] * (1.0f / H_);
    float var  = rq[0] * (1.0f / H_) - mu * mu;
    float rstd = rsqrtf(var + 1e-5f);
    float4 wv = ((const float4*)w)[tid];
    float4 bv = ((const float4*)b)[tid];
    float4 o4;
    o4.x = (v.x - mu) * rstd * wv.x + bv.x;
    o4.y = (v.y - mu) * rstd * wv.y + bv.y;
    o4.z = (v.z - mu) * rstd * wv.z + bv.z;
    o4.w = (v.w - mu) * rstd * wv.w + bv.w;
    ((float4*)(out + (size_t)row * H_))[tid] = o4;
}

// ---------------- Tiled SGEMM, NT: C = A[M,K] * B[N,K]^T (+epilogue) ----------
// EPI: 0 = +bias ; 1 = +bias +residual ; 2 = *scale with causal mask (-1e30)
template<int EPI>
__global__ __launch_bounds__(256) void sgemm_nt(
    const float* __restrict__ A, const float* __restrict__ B,
    float* __restrict__ C, int M, int N, int K,
    int lda, int ldb, int ldc, long sA, long sB, long sC,
    const float* __restrict__ bias, const float* __restrict__ res, float scale)
{
    A += (long)blockIdx.z * sA;
    B += (long)blockIdx.z * sB;
    C += (long)blockIdx.z * sC;
    int row0 = blockIdx.y << 6, col0 = blockIdx.x << 6;
    int tid = threadIdx.x;

    if (EPI == 2 && col0 > row0 + 63) {      // fully above diagonal: skip compute
        for (int i = tid; i < 4096; i += 256)
            C[(long)(row0 + (i >> 6)) * ldc + col0 + (i & 63)] = -1e30f;
        return;
    }

    __shared__ float As[16][64];
    __shared__ float Bs[16][64];
    int tx = tid & 15, ty = tid >> 4;
    int ar = tid >> 2, ac = (tid & 3) << 2;
    float acc[4][4] = {};

    const float* Ap = A + (long)(row0 + ar) * lda + ac;
    const float* Bp = B + (long)(col0 + ar) * ldb + ac;

    for (int k0 = 0; k0 < K; k0 += 16) {
        float4 av = *(const float4*)(Ap + k0);
        float4 bv = *(const float4*)(Bp + k0);
        As[ac  ][ar] = av.x; As[ac+1][ar] = av.y; As[ac+2][ar] = av.z; As[ac+3][ar] = av.w;
        Bs[ac  ][ar] = bv.x; Bs[ac+1][ar] = bv.y; Bs[ac+2][ar] = bv.z; Bs[ac+3][ar] = bv.w;
        __syncthreads();
        #pragma unroll
        for (int kk = 0; kk < 16; ++kk) {
            float a[4], bb[4];
            *(float4*)a  = *(const float4*)&As[kk][ty << 2];
            *(float4*)bb = *(const float4*)&Bs[kk][tx << 2];
            #pragma unroll
            for (int i = 0; i < 4; ++i)
                #pragma unroll
                for (int j = 0; j < 4; ++j)
                    acc[i][j] += a[i] * bb[j];
        }
        __syncthreads();
    }

    #pragma unroll
    for (int i = 0; i < 4; ++i) {
        int r = row0 + (ty << 2) + i;
        #pragma unroll
        for (int j = 0; j < 4; ++j) {
            int c = col0 + (tx << 2) + j;
            float v = acc[i][j];
            if (EPI == 0) v += bias[c];
            else if (EPI == 1) v += bias[c] + res[(long)r * ldc + c];
            else if (EPI == 2) v = (c <= r) ? v * scale : -1e30f;
            C[(long)r * ldc + c] = v;
        }
    }
}

// ---------------- Tiled SGEMM, NN: C = A[M,K] * B[K,N] ----------------
__global__ __launch_bounds__(256) void sgemm_nn(
    const float* __restrict__ A, const float* __restrict__ B,
    float* __restrict__ C, int M, int N, int K,
    int lda, int ldb, int ldc, long sA, long sB, long sC)
{
    A += (long)blockIdx.z * sA;
    B += (long)blockIdx.z * sB;
    C += (long)blockIdx.z * sC;
    int row0 = blockIdx.y << 6, col0 = blockIdx.x << 6;
    int tid = threadIdx.x;

    __shared__ float As[16][64];
    __shared__ float Bs[16][64];
    int tx = tid & 15, ty = tid >> 4;
    int ar = tid >> 2, ac = (tid & 3) << 2;
    int br = tid >> 4, bc = (tid & 15) << 2;
    float acc[4][4] = {};

    const float* Ap = A + (long)(row0 + ar) * lda + ac;
    const float* Bp = B + (long)br * ldb + col0 + bc;

    for (int k0 = 0; k0 < K; k0 += 16) {
        float4 av = *(const float4*)(Ap + k0);
        float4 bv = *(const float4*)(Bp + (long)k0 * ldb);
        As[ac  ][ar] = av.x; As[ac+1][ar] = av.y; As[ac+2][ar] = av.z; As[ac+3][ar] = av.w;
        *(float4*)&Bs[br][bc] = bv;
        __syncthreads();
        #pragma unroll
        for (int kk = 0; kk < 16; ++kk) {
            float a[4], bb[4];
            *(float4*)a  = *(const float4*)&As[kk][ty << 2];
            *(float4*)bb = *(const float4*)&Bs[kk][tx << 2];
            #pragma unroll
            for (int i = 0; i < 4; ++i)
                #pragma unroll
                for (int j = 0; j < 4; ++j)
                    acc[i][j] += a[i] * bb[j];
        }
        __syncthreads();
    }

    #pragma unroll
    for (int i = 0; i < 4; ++i) {
        int r = row0 + (ty << 2) + i;
        #pragma unroll
        for (int j = 0; j < 4; ++j)
            C[(long)r * ldc + col0 + (tx << 2) + j] = acc[i][j];
    }
}

// ---------------- row softmax over 2048 cols (scores in place) -------------
__global__ __launch_bounds__(256) void softmax_kernel(float* __restrict__ sc)
{
    long row = blockIdx.x;
    float* r = sc + row * (long)S_;
    int tid = threadIdx.x;
    float v[8];
    float mx = -INFINITY;
    #pragma unroll
    for (int i = 0; i < 8; ++i) { v[i] = r[tid + i * 256]; mx = fmaxf(mx, v[i]); }
    __shared__ float sm[256];
    sm[tid] = mx; __syncthreads();
    for (int o = 128; o > 0; o >>= 1) {
        if (tid < o) sm[tid] = fmaxf(sm[tid], sm[tid + o]);
        __syncthreads();
    }
    mx = sm[0]; __syncthreads();
    float s = 0.f;
    #pragma unroll
    for (int i = 0; i < 8; ++i) { v[i] = expf(v[i] - mx); s += v[i]; }
    sm[tid] = s; __syncthreads();
    for (int o = 128; o > 0; o >>= 1) {
        if (tid < o) sm[tid] += sm[tid + o];
        __syncthreads();
    }
    float inv = 1.f / sm[0];
    #pragma unroll
    for (int i = 0; i < 8; ++i) r[tid + i * 256] = v[i] * inv;
}

// ---------------- router: logits -> softmax -> top2 ----------------
__global__ __launch_bounds__(128) void router_kernel(
    const float* __restrict__ X, const float* __restrict__ Wr)
{
    int t = blockIdx.x;
    int tid = threadIdx.x;
    float p[8] = {};
    const float* xr = X + (size_t)t * H_;
    for (int h = tid; h < H_; h += 128) {
        float xv = xr[h];
        #pragma unroll
        for (int e = 0; e < 8; ++e) p[e] += xv * Wr[e * H_ + h];
    }
    #pragma unroll
    for (int o = 16; o > 0; o >>= 1)
        #pragma unroll
        for (int e = 0; e < 8; ++e) p[e] += __shfl_xor_sync(0xffffffff, p[e], o);
    __shared__ float sred[4][8];
    int w = tid >> 5, l = tid & 31;
    if (l == 0) {
        #pragma unroll
        for (int e = 0; e < 8; ++e) sred[w][e] = p[e];
    }
    __syncthreads();
    if (tid == 0) {
        float lg[8];
        #pragma unroll
        for (int e = 0; e < 8; ++e) lg[e] = sred[0][e] + sred[1][e] + sred[2][e] + sred[3][e];
        float mx = lg[0];
        #pragma unroll
        for (int e = 1; e < 8; ++e) mx = fmaxf(mx, lg[e]);
        float s = 0.f, pr[8];
        #pragma unroll
        for (int e = 0; e < 8; ++e) { pr[e] = expf(lg[e] - mx); s += pr[e]; }
        float inv = 1.f / s;
        float m0 = -1.f, m1 = -1.f; int i0 = 0, i1 = 0;
        #pragma unroll
        for (int e = 0; e < 8; ++e) {
            float v = pr[e] * inv;
            if (v > m0)      { m1 = m0; i1 = i0; m0 = v; i0 = e; }
            else if (v > m1) { m1 = v; i1 = e; }
        }
        g_topi[t * 2] = i0; g_topi[t * 2 + 1] = i1;
        g_topw[t * 2] = m0; g_topw[t * 2 + 1] = m1;
    }
}

__global__ void zero_cnt_kernel() { if (threadIdx.x < E_) g_cnt[threadIdx.x] = 0; }

__global__ __launch_bounds__(256) void assign_kernel()
{
    int t = blockIdx.x * blockDim.x + threadIdx.x;
    if (t >= S_) return;
    #pragma unroll
    for (int k = 0; k < 2; ++k) {
        int e = g_topi[t * 2 + k];
        int pos = atomicAdd(&g_cnt[e], 1);
        g_ltok [e * S_ + pos] = t;
        g_lslot[e * S_ + pos] = k;
        g_lgate[e * S_ + pos] = g_topw[t * 2 + k];
    }
}

// ---------------- MoE GEMM1: h1 = gelu(gather(hn2) @ w1[e]) ----------------
__global__ __launch_bounds__(256) void moe_gemm1(
    const float* __restrict__ X, const float* __restrict__ w1)
{
    int e = blockIdx.z;
    int cnt = g_cnt[e];
    int row0 = blockIdx.y << 6;
    if (row0 >= cnt) return;
    int col0 = blockIdx.x << 6;
    int tid = threadIdx.x;

    __shared__ int s_tok[64];
    if (tid < 64) {
        int i = row0 + tid;
        s_tok[tid] = (i < cnt) ? g_ltok[e * S_ + i] : -1;
    }
    __syncthreads();

    __shared__ float As[16][64];
    __shared__ float Bs[16][64];
    int tx = tid & 15, ty = tid >> 4;
    int ar = tid >> 2, ac = (tid & 3) << 2;
    int br = tid >> 4, bc = (tid & 15) << 2;
    int tok = s_tok[ar];
    const float* Ap = X + (long)(tok < 0 ? 0 : tok) * H_ + ac;
    const float* Bp = w1 + (long)e * H_ * F_ + (long)br * F_ + col0 + bc;
    float acc[4][4] = {};

    for (int k0 = 0; k0 < H_; k0 += 16) {
        float4 av = (tok >= 0) ? *(const float4*)(Ap + k0) : make_float4(0, 0, 0, 0);
        float4 bv = *(const float4*)(Bp + (long)k0 * F_);
        As[ac  ][ar] = av.x; As[ac+1][ar] = av.y; As[ac+2][ar] = av.z; As[ac+3][ar] = av.w;
        *(float4*)&Bs[br][bc] = bv;
        __syncthreads();
        #pragma unroll
        for (int kk = 0; kk < 16; ++kk) {
            float a[4], bb[4];
            *(float4*)a  = *(const float4*)&As[kk][ty << 2];
            *(float4*)bb = *(const float4*)&Bs[kk][tx << 2];
            #pragma unroll
            for (int i = 0; i < 4; ++i)
                #pragma unroll
                for (int j = 0; j < 4; ++j)
                    acc[i][j] += a[i] * bb[j];
        }
        __syncthreads();
    }

    #pragma unroll
    for (int i = 0; i < 4; ++i) {
        int rl = row0 + (ty << 2) + i;
        if (rl < cnt) {
            #pragma unroll
            for (int j = 0; j < 4; ++j) {
                float v = acc[i][j];
                float gel = 0.5f * v * (1.0f + erff(v * 0.70710678118654752f));
                g_h1[((long)e * S_ + rl) * F_ + col0 + (tx << 2) + j] = gel;
            }
        }
    }
}

// ---------------- MoE GEMM2: contrib[t,slot] = gate * (h1 @ w2[e]) ----------
__global__ __launch_bounds__(256) void moe_gemm2(const float* __restrict__ w2)
{
    int e = blockIdx.z;
    int cnt = g_cnt[e];
    int row0 = blockIdx.y << 6;
    if (row0 >= cnt) return;
    int col0 = blockIdx.x << 6;
    int tid = threadIdx.x;

    __shared__ int   s_tok[64];
    __shared__ int   s_slot[64];
    __shared__ float s_gate[64];
    if (tid < 64) {
        int i = row0 + tid;
        if (i < cnt) {
            s_tok [tid] = g_ltok [e * S_ + i];
            s_slot[tid] = g_lslot[e * S_ + i];
            s_gate[tid] = g_lgate[e * S_ + i];
        } else s_tok[tid] = -1;
    }
    __syncthreads();

    __shared__ float As[16][64];
    __shared__ float Bs[16][64];
    int tx = tid & 15, ty = tid >> 4;
    int ar = tid >> 2, ac = (tid & 3) << 2;
    int br = tid >> 4, bc = (tid & 15) << 2;
    int arow = row0 + ar;
    bool avalid = arow < cnt;
    const float* Ap = g_h1 + ((long)e * S_ + (avalid ? arow : 0)) * F_ + ac;
    const float* Bp = w2 + (long)e * F_ * H_ + (long)br * H_ + col0 + bc;
    float acc[4][4] = {};

    for (int k0 = 0; k0 < F_; k0 += 16) {
        float4 av = avalid ? *(const float4*)(Ap + k0) : make_float4(0, 0, 0, 0);
        float4 bv = *(const float4*)(Bp + (long)k0 * H_);
        As[ac  ][ar] = av.x; As[ac+1][ar] = av.y; As[ac+2][ar] = av.z; As[ac+3][ar] = av.w;
        *(float4*)&Bs[br][bc] = bv;
        __syncthreads();
        #pragma unroll
        for (int kk = 0; kk < 16; ++kk) {
            float a[4], bb[4];
            *(float4*)a  = *(const float4*)&As[kk][ty << 2];
            *(float4*)bb = *(const float4*)&Bs[kk][tx << 2];
            #pragma unroll
            for (int i = 0; i < 4; ++i)
                #pragma unroll
                for (int j = 0; j < 4; ++j)
                    acc[i][j] += a[i] * bb[j];
        }
        __syncthreads();
    }

    #pragma unroll
    for (int i = 0; i < 4; ++i) {
        int lr = (ty << 2) + i;
        int rl = row0 + lr;
        if (rl < cnt) {
            int t = s_tok[lr];
            int slot = s_slot[lr];
            float gate = s_gate[lr];
            #pragma unroll
            for (int j = 0; j < 4; ++j)
                g_contrib[((long)t * 2 + slot) * H_ + col0 + (tx << 2) + j] =
                    gate * acc[i][j];
        }
    }
}

// ---------------- final: out = x1 + contrib0 + contrib1 ----------------
__global__ __launch_bounds__(256) void final_kernel(float* __restrict__ out)
{
    int i = blockIdx.x * blockDim.x + threadIdx.x;
    long t = i >> 10, c = i & 1023;
    out[i] = g_x1[i] + g_contrib[(t * 2) * H_ + c] + g_contrib[(t * 2 + 1) * H_ + c];
}

// ---------------- launcher ----------------
extern "C" void kernel_launch(void* const* d_in, const int* in_sizes, int n_in,
                              void* d_out, int out_size)
{
    const float* x        = (const float*)d_in[0];
    const float* ln1_w    = (const float*)d_in[1];
    const float* ln1_b    = (const float*)d_in[2];
    const float* in_w     = (const float*)d_in[3];
    const float* in_b     = (const float*)d_in[4];
    const float* out_w    = (const float*)d_in[5];
    const float* out_b    = (const float*)d_in[6];
    const float* ln2_w    = (const float*)d_in[7];
    const float* ln2_b    = (const float*)d_in[8];
    const float* router_w = (const float*)d_in[9];
    const float* w1       = (const float*)d_in[10];
    const float* w2       = (const float*)d_in[11];
    float* out = (float*)d_out;

    float *hn, *qkv, *scores, *attn, *x1, *hn2;
    cudaGetSymbolAddress((void**)&hn,     g_hn);
    cudaGetSymbolAddress((void**)&qkv,    g_qkv);
    cudaGetSymbolAddress((void**)&scores, g_scores);
    cudaGetSymbolAddress((void**)&attn,   g_attn);
    cudaGetSymbolAddress((void**)&x1,     g_x1);
    cudaGetSymbolAddress((void**)&hn2,    g_hn2);

    // 1. LN1
    ln_kernel<<<S_, 256>>>(x, ln1_w, ln1_b, hn);

    // 2. QKV = hn @ in_w^T + in_b   [2048, 3072]
    sgemm_nt<0><<<dim3(T3H / 64, S_ / 64, 1), 256>>>(
        hn, in_w, qkv, S_, T3H, H_, H_, H_, T3H, 0, 0, 0, in_b, nullptr, 0.f);

    // 3. scores[h] = (Q_h K_h^T) / 8 with causal mask  [16][2048][2048]
    sgemm_nt<2><<<dim3(S_ / 64, S_ / 64, NH), 256>>>(
        qkv, qkv + H_, scores, S_, S_, HD, T3H, T3H, S_,
        HD, HD, (long)S_ * S_, nullptr, nullptr, 0.125f);

    // 4. softmax rows (in place)
    softmax_kernel<<<NH * S_, 256>>>(scores);

    // 5. attn[:, h*64:...] = P_h @ V_h   (NN, batched over heads)
    sgemm_nn<<<dim3(1, S_ / 64, NH), 256>>>(
        scores, qkv + 2 * H_, attn, S_, HD, S_, S_, T3H, H_,
        (long)S_ * S_, HD, HD);

    // 6. x1 = attn @ out_w^T + out_b + x
    sgemm_nt<1><<<dim3(H_ / 64, S_ / 64, 1), 256>>>(
        attn, out_w, x1, S_, H_, H_, H_, H_, H_, 0, 0, 0, out_b, x, 0.f);

    // 7. LN2
    ln_kernel<<<S_, 256>>>(x1, ln2_w, ln2_b, hn2);

    // 8. router + top-2 + expert compaction
    router_kernel<<<S_, 128>>>(hn2, router_w);
    zero_cnt_kernel<<<1, 32>>>();
    assign_kernel<<<S_ / 256, 256>>>();

    // 9. expert MLP (sparse)
    moe_gemm1<<<dim3(F_ / 64, S_ / 64, E_), 256>>>(hn2, w1);
    moe_gemm2<<<dim3(H_ / 64, S_ / 64, E_), 256>>>(w2);

    // 10. out = x1 + y
    final_kernel<<<(S_ * H_) / 256, 256>>>(out);
}

// round 3
// speedup vs baseline: 2.7571x; 2.7571x over previous
#include <cuda_runtime.h>
#include <math.h>
#include <stdint.h>

// ---------------- problem constants ----------------
#define S_   2048
#define H_   1024
#define NH   16
#define HD   64
#define E_   8
#define F_   2048
#define T3H  3072

// ---------------- device scratch ----------------
__device__ float g_hn     [S_ * H_];
__device__ float g_qkv    [S_ * T3H];
__device__ float g_scores [(size_t)NH * S_ * S_];
__device__ float g_attn   [S_ * H_];
__device__ float g_x1     [S_ * H_];
__device__ float g_hn2    [S_ * H_];
__device__ int   g_topi   [S_ * 2];
__device__ float g_topw   [S_ * 2];
__device__ int   g_cnt    [E_];
__device__ int   g_ltok   [E_ * S_];
__device__ int   g_lslot  [E_ * S_];
__device__ float g_lgate  [E_ * S_];
__device__ float g_h1     [(size_t)E_ * S_ * F_];
__device__ float g_contrib[(size_t)S_ * 2 * H_];

// ---------------- helpers ----------------
__device__ __forceinline__ uint32_t f2t(float f) {
    uint32_t u;
    asm("cvt.rna.tf32.f32 %0, %1;" : "=r"(u) : "f"(f));
    return u;
}
__device__ __forceinline__ void mma8(float* d, const uint32_t* a, const uint32_t* b) {
    asm volatile(
        "mma.sync.aligned.m16n8k8.row.col.f32.tf32.tf32.f32 "
        "{%0,%1,%2,%3}, {%4,%5,%6,%7}, {%8,%9}, {%0,%1,%2,%3};"
        : "+f"(d[0]), "+f"(d[1]), "+f"(d[2]), "+f"(d[3])
        : "r"(a[0]), "r"(a[1]), "r"(a[2]), "r"(a[3]), "r"(b[0]), "r"(b[1]));
}

// ================= tensor-core tf32 GEMM (mma.sync) =================
// MODE: 0=QKV(+bias) 1=QK(causal*0.125) 2=PV 3=OUT(+bias+res) 4=MOE1(gelu) 5=MOE2(gate-scatter)
template<int MODE>
__global__ __launch_bounds__(256) void tc_gemm(
    const float* __restrict__ A, const float* __restrict__ B, float* __restrict__ C,
    const float* __restrict__ bias, const float* __restrict__ res)
{
    constexpr int  NT   = (MODE == 2) ? 64 : 128;      // CTA N tile
    constexpr bool BT   = (MODE == 2 || MODE == 4 || MODE == 5);  // B given [K,N]
    constexpr int  GN   = (NT == 128) ? 4 : 2;         // warp grid
    constexpr int  GM   = 8 / GN;
    constexpr int  WMT  = 128 / (GM * 16);             // m16 frags per warp
    constexpr int  WNT  = NT  / (GN * 8);              // n8 frags per warp
    constexpr int  LDA  = 36;                          // A smem stride (floats)
    constexpr int  LDBN = 36;                          // n-major B stride
    constexpr int  LDBK = NT + 8;                      // k-major B stride
    constexpr int  ASZ  = 128 * LDA;
    constexpr int  BSZ  = BT ? 32 * LDBK : 128 * LDBN;
    constexpr int  TPK  = NT / 4;                      // threads per k-row (BT load)
    constexpr int  ROWS = 256 / TPK;                   // k-rows per pass
    constexpr int  PASS = 32 / ROWS;

    extern __shared__ float sf[];
    float* As = sf;
    float* Bs = sf + ASZ;
    int*   s_tok  = (int*)(sf + ASZ + BSZ);
    int*   s_slot = s_tok + 128;
    float* s_gate = (float*)(s_slot + 128);

    const int tid  = threadIdx.x;
    const int wid  = tid >> 5, lane = tid & 31;
    const int gid  = lane >> 2, tid4 = lane & 3;
    const int bx = blockIdx.x, by = blockIdx.y, bz = blockIdx.z;
    const int row0 = by << 7, col0 = bx * NT;

    const float* Ab = A; const float* Bb = B; float* Cb = C;
    int lda = 0, ldb = 0, ldc = 0, K = 0, cnt = 0;
    if (MODE == 0) { lda = H_; ldb = H_; ldc = T3H; K = H_; }
    else if (MODE == 1) {
        if (bx > by) return;
        Ab = A + bz * HD; Bb = A + H_ + bz * HD; Cb = C + (size_t)bz * S_ * S_;
        lda = T3H; ldb = T3H; ldc = S_; K = HD;
    }
    else if (MODE == 2) {
        Ab = A + (size_t)bz * S_ * S_; Bb = B + 2 * H_ + bz * HD; Cb = C + bz * HD;
        lda = S_; ldb = T3H; ldc = H_; K = row0 + 128;
    }
    else if (MODE == 3) { lda = H_; ldb = H_; ldc = H_; K = H_; }
    else if (MODE == 4) {
        cnt = g_cnt[bz]; if (row0 >= cnt) return;
        lda = H_; Bb = B + (size_t)bz * H_ * F_; ldb = F_;
        Cb = C + (size_t)bz * S_ * F_; ldc = F_; K = H_;
    }
    else {
        cnt = g_cnt[bz]; if (row0 >= cnt) return;
        Ab = A + (size_t)bz * S_ * F_; lda = F_;
        Bb = B + (size_t)bz * F_ * H_; ldb = H_; ldc = H_; K = F_;
    }
    const int niter = K >> 5;

    if ((MODE == 4 || MODE == 5) && tid < 128) {
        int i = row0 + tid;
        if (i < cnt) {
            s_tok[tid] = g_ltok[bz * S_ + i];
            if (MODE == 5) { s_slot[tid] = g_lslot[bz * S_ + i]; s_gate[tid] = g_lgate[bz * S_ + i]; }
        } else { s_tok[tid] = 0; if (MODE == 5) { s_slot[tid] = 0; s_gate[tid] = 0.f; } }
    }
    __syncthreads();

    // ---- staging addresses ----
    const int ra  = tid >> 1;                 // A row in tile
    const int kc  = (tid & 1) * 16;           // A k chunk base
    const float* aRow = (MODE == 4) ? (Ab + (size_t)s_tok[ra] * H_)
                                    : (Ab + (size_t)(row0 + ra) * lda);
    const float* bRowN = nullptr;
    int kr = 0, nc4 = 0;
    if (!BT) bRowN = Bb + (size_t)(col0 + ra) * ldb;
    else { kr = tid / TPK; nc4 = (tid % TPK) * 4; }

    float4 pa[4], pb[4];
    auto PREF = [&](int k0) {
        #pragma unroll
        for (int j = 0; j < 4; ++j) pa[j] = *(const float4*)(aRow + k0 + kc + 4 * j);
        if (!BT) {
            #pragma unroll
            for (int j = 0; j < 4; ++j) pb[j] = *(const float4*)(bRowN + k0 + kc + 4 * j);
        } else {
            #pragma unroll
            for (int p = 0; p < PASS; ++p)
                pb[p] = *(const float4*)(Bb + (size_t)(k0 + kr + p * ROWS) * ldb + col0 + nc4);
        }
    };
    auto STORE = [&]() {
        #pragma unroll
        for (int j = 0; j < 4; ++j) {
            uint4 q = make_uint4(f2t(pa[j].x), f2t(pa[j].y), f2t(pa[j].z), f2t(pa[j].w));
            *(uint4*)(As + ra * LDA + kc + 4 * j) = q;
        }
        if (!BT) {
            #pragma unroll
            for (int j = 0; j < 4; ++j) {
                uint4 q = make_uint4(f2t(pb[j].x), f2t(pb[j].y), f2t(pb[j].z), f2t(pb[j].w));
                *(uint4*)(Bs + ra * LDBN + kc + 4 * j) = q;
            }
        } else {
            #pragma unroll
            for (int p = 0; p < PASS; ++p) {
                uint4 q = make_uint4(f2t(pb[p].x), f2t(pb[p].y), f2t(pb[p].z), f2t(pb[p].w));
                *(uint4*)(Bs + (kr + p * ROWS) * LDBK + nc4) = q;
            }
        }
    };

    const int warpM = wid / GN, warpN = wid % GN;
    const int wm0 = warpM * (WMT * 16), wn0 = warpN * (WNT * 8);
    float acc[WMT][WNT][4] = {};

    PREF(0); STORE();
    __syncthreads();

    for (int it = 0; it < niter; ++it) {
        if (it + 1 < niter) PREF((it + 1) << 5);
        #pragma unroll
        for (int ks = 0; ks < 4; ++ks) {
            const int k0 = ks * 8;
            uint32_t af[WMT][4], bf[WNT][2];
            #pragma unroll
            for (int mi = 0; mi < WMT; ++mi) {
                const float* p = As + (wm0 + mi * 16 + gid) * LDA + k0 + tid4;
                af[mi][0] = *(const uint32_t*)(p);
                af[mi][1] = *(const uint32_t*)(p + 8 * LDA);
                af[mi][2] = *(const uint32_t*)(p + 4);
                af[mi][3] = *(const uint32_t*)(p + 8 * LDA + 4);
            }
            #pragma unroll
            for (int ni = 0; ni < WNT; ++ni) {
                if (!BT) {
                    const float* p = Bs + (wn0 + ni * 8 + gid) * LDBN + k0 + tid4;
                    bf[ni][0] = *(const uint32_t*)(p);
                    bf[ni][1] = *(const uint32_t*)(p + 4);
                } else {
                    const float* p = Bs + (k0 + tid4) * LDBK + wn0 + ni * 8 + gid;
                    bf[ni][0] = *(const uint32_t*)(p);
                    bf[ni][1] = *(const uint32_t*)(p + 4 * LDBK);
                }
            }
            #pragma unroll
            for (int mi = 0; mi < WMT; ++mi)
                #pragma unroll
                for (int ni = 0; ni < WNT; ++ni)
                    mma8(acc[mi][ni], af[mi], bf[ni]);
        }
        if (it + 1 < niter) {
            __syncthreads();
            STORE();
            __syncthreads();
        }
    }

    // ---- epilogue ----
    #pragma unroll
    for (int mi = 0; mi < WMT; ++mi) {
        #pragma unroll
        for (int h = 0; h < 2; ++h) {
            const int rl = wm0 + mi * 16 + gid + 8 * h;
            const int grow = row0 + rl;
            bool rv = true;
            float gate = 1.f;
            float* crow;
            if (MODE == 5) {
                rv = grow < cnt;
                crow = Cb + ((size_t)s_tok[rl] * 2 + s_slot[rl]) * H_;
                gate = s_gate[rl];
            } else if (MODE == 4) {
                rv = grow < cnt;
                crow = Cb + (size_t)grow * ldc;
            } else {
                crow = Cb + (size_t)grow * ldc;
            }
            if (!rv) continue;
            #pragma unroll
            for (int ni = 0; ni < WNT; ++ni) {
                const int c = col0 + wn0 + ni * 8 + tid4 * 2;
                float v0 = acc[mi][ni][2 * h + 0];
                float v1 = acc[mi][ni][2 * h + 1];
                if (MODE == 0) {
                    v0 += bias[c]; v1 += bias[c + 1];
                } else if (MODE == 1) {
                    v0 = (c     <= grow) ? v0 * 0.125f : -1e30f;
                    v1 = (c + 1 <= grow) ? v1 * 0.125f : -1e30f;
                } else if (MODE == 3) {
                    const float* rr = res + (size_t)grow * H_;
                    v0 += bias[c]     + rr[c];
                    v1 += bias[c + 1] + rr[c + 1];
                } else if (MODE == 4) {
                    v0 = 0.5f * v0 * (1.f + erff(v0 * 0.70710678118654752f));
                    v1 = 0.5f * v1 * (1.f + erff(v1 * 0.70710678118654752f));
                } else if (MODE == 5) {
                    v0 *= gate; v1 *= gate;
                }
                *(float2*)(crow + c) = make_float2(v0, v1);
            }
        }
    }
}

// ---------------- LayerNorm ----------------
__global__ __launch_bounds__(256) void ln_kernel(
    const float* __restrict__ x, const float* __restrict__ w,
    const float* __restrict__ b, float* __restrict__ out)
{
    int row = blockIdx.x;
    int tid = threadIdx.x;
    const float4* xr = (const float4*)(x + (size_t)row * H_);
    float4 v = xr[tid];
    float s  = v.x + v.y + v.z + v.w;
    float ss = v.x*v.x + v.y*v.y + v.z*v.z + v.w*v.w;
    __shared__ float rs[256], rq[256];
    rs[tid] = s; rq[tid] = ss;
    __syncthreads();
    for (int o = 128; o > 0; o >>= 1) {
        if (tid < o) { rs[tid] += rs[tid + o]; rq[tid] += rq[tid + o]; }
        __syncthreads();
    }
    float mu   = rs[0] * (1.0f / H_);
    float var  = rq[0] * (1.0f / H_) - mu * mu;
    float rstd = rsqrtf(var + 1e-5f);
    float4 wv = ((const float4*)w)[tid];
    float4 bv = ((const float4*)b)[tid];
    float4 o4;
    o4.x = (v.x - mu) * rstd * wv.x + bv.x;
    o4.y = (v.y - mu) * rstd * wv.y + bv.y;
    o4.z = (v.z - mu) * rstd * wv.z + bv.z;
    o4.w = (v.w - mu) * rstd * wv.w + bv.w;
    ((float4*)(out + (size_t)row * H_))[tid] = o4;
}

// ---------------- causal row softmax (variable length) ----------------
__global__ __launch_bounds__(256) void softmax_kernel(float* __restrict__ sc)
{
    int gr = blockIdx.x;
    int r  = gr & (S_ - 1);
    float* rowp = sc + (size_t)gr * S_;
    int L = ((r >> 7) + 1) << 7;     // = exactly the written region
    int tid = threadIdx.x;
    float v[8]; int n = 0;
    float mx = -INFINITY;
    for (int c = tid; c < L; c += 256) { v[n] = rowp[c]; mx = fmaxf(mx, v[n]); ++n; }
    __shared__ float smr[256];
    smr[tid] = mx; __syncthreads();
    for (int o = 128; o > 0; o >>= 1) {
        if (tid < o) smr[tid] = fmaxf(smr[tid], smr[tid + o]);
        __syncthreads();
    }
    mx = smr[0]; __syncthreads();
    float s = 0.f;
    for (int i = 0; i < n; ++i) { v[i] = __expf(v[i] - mx); s += v[i]; }
    smr[tid] = s; __syncthreads();
    for (int o = 128; o > 0; o >>= 1) {
        if (tid < o) smr[tid] += smr[tid + o];
        __syncthreads();
    }
    float inv = 1.f / smr[0];
    n = 0;
    for (int c = tid; c < L; c += 256) { rowp[c] = v[n] * inv; ++n; }
}

// ---------------- router: logits -> softmax -> top2 ----------------
__global__ __launch_bounds__(128) void router_kernel(
    const float* __restrict__ X, const float* __restrict__ Wr)
{
    int t = blockIdx.x;
    int tid = threadIdx.x;
    float p[8] = {};
    const float* xr = X + (size_t)t * H_;
    for (int h = tid; h < H_; h += 128) {
        float xv = xr[h];
        #pragma unroll
        for (int e = 0; e < 8; ++e) p[e] += xv * Wr[e * H_ + h];
    }
    #pragma unroll
    for (int o = 16; o > 0; o >>= 1)
        #pragma unroll
        for (int e = 0; e < 8; ++e) p[e] += __shfl_xor_sync(0xffffffff, p[e], o);
    __shared__ float sred[4][8];
    int w = tid >> 5, l = tid & 31;
    if (l == 0) {
        #pragma unroll
        for (int e = 0; e < 8; ++e) sred[w][e] = p[e];
    }
    __syncthreads();
    if (tid == 0) {
        float lg[8];
        #pragma unroll
        for (int e = 0; e < 8; ++e) lg[e] = sred[0][e] + sred[1][e] + sred[2][e] + sred[3][e];
        float mx = lg[0];
        #pragma unroll
        for (int e = 1; e < 8; ++e) mx = fmaxf(mx, lg[e]);
        float s = 0.f, pr[8];
        #pragma unroll
        for (int e = 0; e < 8; ++e) { pr[e] = expf(lg[e] - mx); s += pr[e]; }
        float inv = 1.f / s;
        float m0 = -1.f, m1 = -1.f; int i0 = 0, i1 = 0;
        #pragma unroll
        for (int e = 0; e < 8; ++e) {
            float vv = pr[e] * inv;
            if (vv > m0)      { m1 = m0; i1 = i0; m0 = vv; i0 = e; }
            else if (vv > m1) { m1 = vv; i1 = e; }
        }
        g_topi[t * 2] = i0; g_topi[t * 2 + 1] = i1;
        g_topw[t * 2] = m0; g_topw[t * 2 + 1] = m1;
    }
}

__global__ void zero_cnt_kernel() { if (threadIdx.x < E_) g_cnt[threadIdx.x] = 0; }

__global__ __launch_bounds__(256) void assign_kernel()
{
    int t = blockIdx.x * blockDim.x + threadIdx.x;
    if (t >= S_) return;
    #pragma unroll
    for (int k = 0; k < 2; ++k) {
        int e = g_topi[t * 2 + k];
        int pos = atomicAdd(&g_cnt[e], 1);
        g_ltok [e * S_ + pos] = t;
        g_lslot[e * S_ + pos] = k;
        g_lgate[e * S_ + pos] = g_topw[t * 2 + k];
    }
}

// ---------------- final: out = x1 + contrib0 + contrib1 ----------------
__global__ __launch_bounds__(256) void final_kernel(float* __restrict__ out)
{
    int i = blockIdx.x * blockDim.x + threadIdx.x;
    long t = i >> 10, c = i & 1023;
    out[i] = g_x1[i] + g_contrib[(t * 2) * H_ + c] + g_contrib[(t * 2 + 1) * H_ + c];
}

// ---------------- launcher ----------------
extern "C" void kernel_launch(void* const* d_in, const int* in_sizes, int n_in,
                              void* d_out, int out_size)
{
    const float* x        = (const float*)d_in[0];
    const float* ln1_w    = (const float*)d_in[1];
    const float* ln1_b    = (const float*)d_in[2];
    const float* in_w     = (const float*)d_in[3];
    const float* in_b     = (const float*)d_in[4];
    const float* out_w    = (const float*)d_in[5];
    const float* out_b    = (const float*)d_in[6];
    const float* ln2_w    = (const float*)d_in[7];
    const float* ln2_b    = (const float*)d_in[8];
    const float* router_w = (const float*)d_in[9];
    const float* w1       = (const float*)d_in[10];
    const float* w2       = (const float*)d_in[11];
    float* out = (float*)d_out;

    float *hn, *qkv, *scores, *attn, *x1, *hn2, *h1p, *ctb;
    cudaGetSymbolAddress((void**)&hn,     g_hn);
    cudaGetSymbolAddress((void**)&qkv,    g_qkv);
    cudaGetSymbolAddress((void**)&scores, g_scores);
    cudaGetSymbolAddress((void**)&attn,   g_attn);
    cudaGetSymbolAddress((void**)&x1,     g_x1);
    cudaGetSymbolAddress((void**)&hn2,    g_hn2);
    cudaGetSymbolAddress((void**)&h1p,    g_h1);
    cudaGetSymbolAddress((void**)&ctb,    g_contrib);

    const int SMEM = (128 * 36 + 128 * 36) * 4 + 1536;   // 38400 B < 48K default

    // 1. LN1
    ln_kernel<<<S_, 256>>>(x, ln1_w, ln1_b, hn);
    // 2. QKV = hn @ in_w^T + in_b
    tc_gemm<0><<<dim3(T3H / 128, S_ / 128, 1), 256, SMEM>>>(hn, in_w, qkv, in_b, nullptr);
    // 3. scores = causal(Q K^T / 8)  (upper tiles never touched)
    tc_gemm<1><<<dim3(S_ / 128, S_ / 128, NH), 256, SMEM>>>(qkv, nullptr, scores, nullptr, nullptr);
    // 4. causal softmax
    softmax_kernel<<<NH * S_, 256>>>(scores);
    // 5. attn = P @ V (k-loop bounded at diagonal)
    tc_gemm<2><<<dim3(1, S_ / 128, NH), 256, SMEM>>>(scores, qkv, attn, nullptr, nullptr);
    // 6. x1 = attn @ out_w^T + out_b + x
    tc_gemm<3><<<dim3(H_ / 128, S_ / 128, 1), 256, SMEM>>>(attn, out_w, x1, out_b, x);
    // 7. LN2
    ln_kernel<<<S_, 256>>>(x1, ln2_w, ln2_b, hn2);
    // 8. router + top-2 + compaction
    router_kernel<<<S_, 128>>>(hn2, router_w);
    zero_cnt_kernel<<<1, 32>>>();
    assign_kernel<<<S_ / 256, 256>>>();
    // 9. expert MLP (sparse)
    tc_gemm<4><<<dim3(F_ / 128, S_ / 128, E_), 256, SMEM>>>(hn2, w1, h1p, nullptr, nullptr);
    tc_gemm<5><<<dim3(H_ / 128, S_ / 128, E_), 256, SMEM>>>(h1p, w2, ctb, nullptr, nullptr);
    // 10. out = x1 + y
    final_kernel<<<(S_ * H_) / 256, 256>>>(out);
}